// round 4
// baseline (speedup 1.0000x reference)
#include <cuda_runtime.h>
#include <math.h>

#define HID 128
#define NOP 50000
#define NMA 1000
#define NJOB 5000
#define NALL 56000
#define NLAYERS 3
#define EMAX 150000

// ---------------- device scratch (static globals; no allocation) ----------------
__device__ float g_x[NALL * HID];      // current node features (op | ma | job)
__device__ float g_agg[NALL * HID];    // per-layer aggregation buffer
__device__ float g_xs[NOP * HID];      // src projection for current relation
__device__ float g_as[NOP * 8];        // attention src dots
__device__ float g_ad[NOP * 8];        // attention dst dots
__device__ float g_ae[EMAX * 8];       // attention edge dots
__device__ float g_logit[EMAX * 8];    // logits -> exp values
__device__ unsigned g_maxenc[NOP * 8]; // encoded segment max
__device__ float g_den[NOP * 8];       // softmax denominators
__device__ float g_ws[15 * HID * 8];   // folded Wg*att_s  [slot][k][8]
__device__ float g_wd[15 * HID * 8];   // folded Wg*att_d
__device__ float g_Me[15 * 32 * 8];    // folded We_proj @ (Wge*att_e)
__device__ float g_ce[15 * 8];         // folded be_proj @ (Wge*att_e)
__device__ double g_sum[3 * HID];
__device__ double g_sumsq[3 * HID];
__device__ float g_scale[3 * HID];
__device__ float g_shift[3 * HID];

// ---------------- helpers ----------------
__device__ __forceinline__ unsigned enc_f(float f) {
    unsigned u = __float_as_uint(f);
    return (u & 0x80000000u) ? ~u : (u | 0x80000000u);
}
__device__ __forceinline__ float dec_f(unsigned u) {
    return (u & 0x80000000u) ? __uint_as_float(u & 0x7fffffffu) : __uint_as_float(~u);
}

// ---------------- fold kernel: per (layer, edge-type) attention weight folds ----------------
__global__ void fold_kernel(const float* __restrict__ Wg, const float* __restrict__ att_s,
                            const float* __restrict__ att_d, const float* __restrict__ Wge,
                            const float* __restrict__ att_e, const float* __restrict__ We_proj,
                            const float* __restrict__ be_proj) {
    int slot = blockIdx.x;          // i*5 + t
    int i = slot / 5, t = slot % 5;
    int H = (i < NLAYERS - 1) ? 8 : 1;
    int C = HID / H;
    int k = threadIdx.x;            // 0..127
    const float* Wg_  = Wg  + (size_t)slot * HID * HID;
    const float* Wge_ = Wge + (size_t)slot * HID * HID;
    const float* as_  = att_s + slot * HID;
    const float* ad_  = att_d + slot * HID;
    const float* ae_  = att_e + slot * HID;

    float ws[8] = {0,0,0,0,0,0,0,0};
    float wd[8] = {0,0,0,0,0,0,0,0};
    float we[8] = {0,0,0,0,0,0,0,0};
    for (int j = 0; j < HID; j++) {
        int h = j / C;
        float w1 = Wg_[k * HID + j];
        ws[h] += w1 * as_[j];
        wd[h] += w1 * ad_[j];
        float w2 = Wge_[k * HID + j];
        we[h] += w2 * ae_[j];
    }
    #pragma unroll
    for (int h = 0; h < 8; h++) {
        g_ws[slot * HID * 8 + k * 8 + h] = ws[h];
        g_wd[slot * HID * 8 + k * 8 + h] = wd[h];
    }
    __shared__ float wef[HID * 8];
    #pragma unroll
    for (int h = 0; h < 8; h++) wef[k * 8 + h] = we[h];
    __syncthreads();

    // Me[k<32][h] = sum_j We_proj[t][k][j] * wef[j][h]
    if (k < 32) {
        const float* Wep = We_proj + (size_t)t * 32 * HID + (size_t)k * HID;
        float me[8] = {0,0,0,0,0,0,0,0};
        for (int j = 0; j < HID; j++) {
            float v = Wep[j];
            #pragma unroll
            for (int h = 0; h < 8; h++) me[h] += v * wef[j * 8 + h];
        }
        #pragma unroll
        for (int h = 0; h < 8; h++) g_Me[slot * 32 * 8 + k * 8 + h] = me[h];
    }
    if (k == 32) {
        const float* bep = be_proj + t * HID;
        float ce[8] = {0,0,0,0,0,0,0,0};
        for (int j = 0; j < HID; j++) {
            float v = bep[j];
            #pragma unroll
            for (int h = 0; h < 8; h++) ce[h] += v * wef[j * 8 + h];
        }
        #pragma unroll
        for (int h = 0; h < 8; h++) g_ce[slot * 8 + h] = ce[h];
    }
}

// ---------------- generic SGEMM: C[M,128] = A[M,K] @ B[K,128] (+bias) ----------------
__global__ __launch_bounds__(256) void gemm_k(const float* __restrict__ A,
                                              const float* __restrict__ B,
                                              const float* __restrict__ bias,
                                              float* __restrict__ C, int M, int K) {
    __shared__ float As[32][132];
    __shared__ float Bs[32][128];
    int tid = threadIdx.x;
    int tx = tid % 16, ty = tid / 16;
    int row0 = blockIdx.x * 128;
    float acc[8][8];
    #pragma unroll
    for (int r = 0; r < 8; r++)
        #pragma unroll
        for (int c = 0; c < 8; c++) acc[r][c] = 0.f;

    for (int kk = 0; kk < K; kk += 32) {
        int BK = min(32, K - kk);
        for (int idx = tid; idx < 128 * BK; idx += 256) {
            int r = idx / BK, k = idx % BK;
            int gr = row0 + r;
            As[k][r] = (gr < M) ? A[(size_t)gr * K + kk + k] : 0.f;
        }
        for (int idx = tid; idx < 128 * BK; idx += 256) {
            int k = idx / 128, c = idx % 128;
            Bs[k][c] = B[(size_t)(kk + k) * 128 + c];
        }
        __syncthreads();
        #pragma unroll 8
        for (int k = 0; k < BK; k++) {
            float a[8], b[8];
            #pragma unroll
            for (int r = 0; r < 8; r++) a[r] = As[k][ty * 8 + r];
            #pragma unroll
            for (int c = 0; c < 8; c++) b[c] = Bs[k][tx * 8 + c];
            #pragma unroll
            for (int r = 0; r < 8; r++)
                #pragma unroll
                for (int c = 0; c < 8; c++) acc[r][c] += a[r] * b[c];
        }
        __syncthreads();
    }
    #pragma unroll
    for (int r = 0; r < 8; r++) {
        int gr = row0 + ty * 8 + r;
        if (gr < M) {
            #pragma unroll
            for (int c = 0; c < 8; c++) {
                int gc = tx * 8 + c;
                float v = acc[r][c];
                if (bias) v += bias[gc];
                C[(size_t)gr * 128 + gc] = v;
            }
        }
    }
}

// ---------------- node dot: out[n,h] = x[n,:] @ w[:,h] (w stored [128][8]) ----------------
__global__ void node_dot_kernel(const float* __restrict__ x, const float* __restrict__ w,
                                float* __restrict__ out, int n, int H) {
    int gw = (blockIdx.x * blockDim.x + threadIdx.x) >> 5;
    int lane = threadIdx.x & 31;
    if (gw >= n) return;
    const float* xr = x + (size_t)gw * HID;
    float acc[8] = {0,0,0,0,0,0,0,0};
    for (int k = lane; k < HID; k += 32) {
        float xv = xr[k];
        #pragma unroll
        for (int h = 0; h < 8; h++) acc[h] += xv * w[k * 8 + h];
    }
    #pragma unroll
    for (int off = 16; off > 0; off >>= 1)
        #pragma unroll
        for (int h = 0; h < 8; h++) acc[h] += __shfl_xor_sync(0xffffffffu, acc[h], off);
    if (lane == 0)
        for (int h = 0; h < H; h++) out[gw * H + h] = acc[h];
}

// ---------------- a_e = ea_raw[E,32] @ Me[32,8] + ce ----------------
__global__ void edge_ae_kernel(const float* __restrict__ ea, const float* __restrict__ Me,
                               const float* __restrict__ ce, float* __restrict__ out,
                               int E, int H) {
    __shared__ float sMe[32 * 8];
    __shared__ float sce[8];
    int tid = threadIdx.x;
    if (tid < 256) sMe[tid] = Me[tid];
    if (tid < 8) sce[tid] = ce[tid];
    __syncthreads();
    int e = blockIdx.x * blockDim.x + tid;
    if (e >= E) return;
    const float* er = ea + (size_t)e * 32;
    float acc[8];
    #pragma unroll
    for (int h = 0; h < 8; h++) acc[h] = sce[h];
    #pragma unroll 8
    for (int k = 0; k < 32; k++) {
        float v = er[k];
        #pragma unroll
        for (int h = 0; h < 8; h++) acc[h] += v * sMe[k * 8 + h];
    }
    for (int h = 0; h < H; h++) out[e * H + h] = acc[h];
}

// ---------------- zero max/den ----------------
__global__ void zero_md_kernel(int n) {
    int i = blockIdx.x * blockDim.x + threadIdx.x;
    if (i < n) { g_maxenc[i] = 0u; g_den[i] = 0.f; }
}

// ---------------- edge pass 1: logits + segment max ----------------
__global__ void edge_max_kernel(const int* __restrict__ EI, int E, int H) {
    int e = blockIdx.x * blockDim.x + threadIdx.x;
    if (e >= E) return;
    int src = EI[e], dst = EI[E + e];
    for (int h = 0; h < H; h++) {
        float l = g_as[src * H + h] + g_ad[dst * H + h] + g_ae[e * H + h];
        l = (l > 0.f) ? l : 0.2f * l;
        g_logit[e * H + h] = l;
        atomicMax(&g_maxenc[dst * H + h], enc_f(l));
    }
}

// ---------------- edge pass 2: exp + denominator ----------------
__global__ void edge_den_kernel(const int* __restrict__ EI, int E, int H) {
    int e = blockIdx.x * blockDim.x + threadIdx.x;
    if (e >= E) return;
    int dst = EI[E + e];
    for (int h = 0; h < H; h++) {
        float m = dec_f(g_maxenc[dst * H + h]);
        float ex = expf(g_logit[e * H + h] - m);
        g_logit[e * H + h] = ex;
        atomicAdd(&g_den[dst * H + h], ex);
    }
}

// ---------------- edge pass 3: weighted message scatter ----------------
__global__ void edge_msg_kernel(const int* __restrict__ EI, int E, int H, int C,
                                int dstoff) {
    int gw = (blockIdx.x * blockDim.x + threadIdx.x) >> 5;
    int lane = threadIdx.x & 31;
    if (gw >= E) return;
    int src = EI[gw], dst = EI[E + gw];
    float al = 0.f;
    if (lane < H) al = g_logit[gw * H + lane] / (g_den[dst * H + lane] + 1e-16f);
    int c = lane * 4;
    float a = __shfl_sync(0xffffffffu, al, c / C);
    const float4 xv = *reinterpret_cast<const float4*>(g_xs + (size_t)src * HID + c);
    float* p = g_agg + (size_t)dstoff + (size_t)dst * HID + c;
    atomicAdd(p + 0, xv.x * a);
    atomicAdd(p + 1, xv.y * a);
    atomicAdd(p + 2, xv.z * a);
    atomicAdd(p + 3, xv.w * a);
}

// ---------------- init agg with per-type bias sums; zero BN stats ----------------
__global__ void init_agg_kernel(const float* __restrict__ bg, int layer) {
    int idx = blockIdx.x * blockDim.x + threadIdx.x;
    if (idx < 3 * HID) { g_sum[idx] = 0.0; g_sumsq[idx] = 0.0; }
    if (idx >= NALL * HID) return;
    int row = idx / HID, col = idx % HID;
    const float* b = bg + layer * 5 * HID;
    float v;
    if (row < NOP)            v = b[0 * HID + col] + b[2 * HID + col] + b[3 * HID + col];
    else if (row < NOP + NMA) v = b[1 * HID + col];
    else                      v = b[4 * HID + col];
    g_agg[idx] = v;
}

// ---------------- BN statistics ----------------
__global__ void bn_stats_kernel() {
    const int offs[3] = {0, NOP, NOP + NMA};
    const int cnts[3] = {NOP, NMA, NJOB};
    int type = blockIdx.y;
    int col = threadIdx.x;
    int N = cnts[type], off = offs[type];
    double s = 0.0, s2 = 0.0;
    for (int r = blockIdx.x; r < N; r += gridDim.x) {
        float v = g_agg[(size_t)(off + r) * HID + col];
        s += (double)v;
        s2 += (double)v * (double)v;
    }
    atomicAdd(&g_sum[type * HID + col], s);
    atomicAdd(&g_sumsq[type * HID + col], s2);
}

__global__ void bn_finalize_kernel(const float* __restrict__ gamma,
                                   const float* __restrict__ beta, int layer) {
    const int cnts[3] = {NOP, NMA, NJOB};
    int idx = threadIdx.x + blockIdx.x * blockDim.x;
    if (idx >= 3 * HID) return;
    int type = idx / HID, col = idx % HID;
    double N = (double)cnts[type];
    double mu = g_sum[idx] / N;
    double var = g_sumsq[idx] / N - mu * mu;
    if (var < 0.0) var = 0.0;
    float g = gamma[layer * 3 * HID + type * HID + col];
    float b = beta[layer * 3 * HID + type * HID + col];
    float sc = g * rsqrtf((float)var + 1e-5f);
    g_scale[idx] = sc;
    g_shift[idx] = b - (float)mu * sc;
}

// ---------------- BN apply + relu + residual (in place on g_x) ----------------
__global__ void bn_apply_kernel(int layer) {
    int idx = blockIdx.x * blockDim.x + threadIdx.x;
    if (idx >= NALL * HID) return;
    int row = idx / HID, col = idx % HID;
    int type = (row < NOP) ? 0 : ((row < NOP + NMA) ? 1 : 2);
    float v = g_agg[idx] * g_scale[type * HID + col] + g_shift[type * HID + col];
    if (layer < NLAYERS - 1) v = fmaxf(v, 0.f);
    g_x[idx] = g_x[idx] + v;
}

// ---------------- launch ----------------
extern "C" void kernel_launch(void* const* d_in, const int* in_sizes, int n_in,
                              void* d_out, int out_size) {
    const float* x_op  = (const float*)d_in[0];
    const float* x_ma  = (const float*)d_in[1];
    const float* x_job = (const float*)d_in[2];

    // Edge inputs: setup_inputs() inserts them INTERLEAVED (ei_t, ea_t per
    // relation), while the reference signature groups them. Detect which
    // layout metadata.txt used from in_sizes: d_in[4] is ea_prec (E*32 =
    // 4,800,000 floats) if interleaved, or ei_assign (2*E = 200,000 ints)
    // if grouped.
    const int* EI[5];
    const float* EA[5];
    bool interleaved = (in_sizes[4] > 1000000);
    if (interleaved) {
        for (int t = 0; t < 5; t++) {
            EI[t] = (const int*)d_in[3 + 2 * t];
            EA[t] = (const float*)d_in[4 + 2 * t];
        }
    } else {
        for (int t = 0; t < 5; t++) {
            EI[t] = (const int*)d_in[3 + t];
            EA[t] = (const float*)d_in[8 + t];
        }
    }

    const float* Wn_op = (const float*)d_in[13];
    const float* bn_op = (const float*)d_in[14];
    const float* Wn_ma = (const float*)d_in[15];
    const float* bn_ma = (const float*)d_in[16];
    const float* Wn_job = (const float*)d_in[17];
    const float* bn_job = (const float*)d_in[18];
    const float* We_proj = (const float*)d_in[19];
    const float* be_proj = (const float*)d_in[20];
    const float* Wg    = (const float*)d_in[21];
    const float* att_s = (const float*)d_in[22];
    const float* att_d = (const float*)d_in[23];
    const float* Wge   = (const float*)d_in[24];
    const float* att_e = (const float*)d_in[25];
    const float* bg    = (const float*)d_in[26];
    const float* gamma = (const float*)d_in[27];
    const float* beta  = (const float*)d_in[28];
    const float* Wo    = (const float*)d_in[29];
    const float* bo    = (const float*)d_in[30];

    static const int Esz[5]  = {150000, 100000, 150000, 100000, 100000};
    static const int Tsrc[5] = {0, 0, 1, 2, 0};
    static const int Tdst[5] = {0, 1, 0, 0, 2};
    static const int offn[3] = {0, NOP, NOP + NMA};
    static const int cntn[3] = {NOP, NMA, NJOB};

    float* gx;   cudaGetSymbolAddress((void**)&gx, g_x);
    float* gxs;  cudaGetSymbolAddress((void**)&gxs, g_xs);
    float* gas;  cudaGetSymbolAddress((void**)&gas, g_as);
    float* gad;  cudaGetSymbolAddress((void**)&gad, g_ad);
    float* gae;  cudaGetSymbolAddress((void**)&gae, g_ae);
    float* gws;  cudaGetSymbolAddress((void**)&gws, g_ws);
    float* gwd;  cudaGetSymbolAddress((void**)&gwd, g_wd);
    float* gMe;  cudaGetSymbolAddress((void**)&gMe, g_Me);
    float* gce;  cudaGetSymbolAddress((void**)&gce, g_ce);

    // 1) fold attention weights (all layers/types)
    fold_kernel<<<15, 128>>>(Wg, att_s, att_d, Wge, att_e, We_proj, be_proj);

    // 2) node input projections
    gemm_k<<<(NOP + 127) / 128, 256>>>(x_op, Wn_op, bn_op, gx, NOP, 64);
    gemm_k<<<(NMA + 127) / 128, 256>>>(x_ma, Wn_ma, bn_ma, gx + (size_t)NOP * HID, NMA, 32);
    gemm_k<<<(NJOB + 127) / 128, 256>>>(x_job, Wn_job, bn_job, gx + (size_t)(NOP + NMA) * HID, NJOB, 16);

    // 3) layers
    for (int i = 0; i < NLAYERS; i++) {
        int H = (i < NLAYERS - 1) ? 8 : 1;
        int C = HID / H;
        init_agg_kernel<<<(NALL * HID + 255) / 256, 256>>>(bg, i);
        for (int t = 0; t < 5; t++) {
            int slot = i * 5 + t;
            int st = Tsrc[t], dt = Tdst[t];
            int E = Esz[t];
            int nsrc = cntn[st], ndst = cntn[dt];
            const float* xsrc = gx + (size_t)offn[st] * HID;
            const float* xdst = gx + (size_t)offn[dt] * HID;
            // full src projection (needed for messages)
            gemm_k<<<(nsrc + 127) / 128, 256>>>(xsrc, Wg + (size_t)slot * HID * HID,
                                                nullptr, gxs, nsrc, HID);
            // folded attention dots
            node_dot_kernel<<<(nsrc * 32 + 255) / 256, 256>>>(xsrc, gws + slot * HID * 8, gas, nsrc, H);
            node_dot_kernel<<<(ndst * 32 + 255) / 256, 256>>>(xdst, gwd + slot * HID * 8, gad, ndst, H);
            edge_ae_kernel<<<(E + 255) / 256, 256>>>(EA[t], gMe + slot * 32 * 8,
                                                     gce + slot * 8, gae, E, H);
            // segment softmax + scatter
            zero_md_kernel<<<(ndst * H + 255) / 256, 256>>>(ndst * H);
            edge_max_kernel<<<(E + 255) / 256, 256>>>(EI[t], E, H);
            edge_den_kernel<<<(E + 255) / 256, 256>>>(EI[t], E, H);
            edge_msg_kernel<<<(E * 32 + 255) / 256, 256>>>(EI[t], E, H, C, offn[dt] * HID);
        }
        // BatchNorm + relu + residual
        dim3 sg(64, 3);
        bn_stats_kernel<<<sg, 128>>>();
        bn_finalize_kernel<<<2, 256>>>(gamma, beta, i);
        bn_apply_kernel<<<(NALL * HID + 255) / 256, 256>>>(i);
    }

    // 4) output projection
    gemm_k<<<(NOP + 127) / 128, 256>>>(gx, Wo, bo, (float*)d_out, NOP, HID);
}

// round 6
// speedup vs baseline: 1.2892x; 1.2892x over previous
#include <cuda_runtime.h>
#include <math.h>

#define HID 128
#define NOP 50000
#define NMA 1000
#define NJOB 5000
#define NALL 56000
#define NLAYERS 3
#define EMAX 150000
#define FULLMASK 0xffffffffu

// ---------------- device scratch ----------------
__device__ float g_x[NALL * HID];        // node features (op | ma | job)
__device__ float g_agg[NALL * HID];      // per-layer aggregation
__device__ float g_xs3[NOP * 384];       // merged src proj for relations 0,1,4
__device__ float g_xsm[NMA * HID];       // src proj relation 2 (machine)
__device__ float g_xsj[NJOB * HID];      // src proj relation 3 (job)
__device__ float g_as[NOP * 8];          // attention src dots (reused per relation)
__device__ float g_ad[NOP * 8];          // attention dst dots
__device__ float g_aes[EMAX * 8];        // edge attention dots, CSR-sorted order
__device__ float g_ws[15 * HID * 8];     // folded Wg*att_s
__device__ float g_wd[15 * HID * 8];     // folded Wg*att_d
__device__ float g_Me[15 * 32 * 8];      // folded We_proj @ (Wge*att_e)
__device__ float g_ce[15 * 8];
__device__ float g_Wcat[3 * HID * 384];  // per-layer concat of Wg[i,{0,1,4}]
// CSR (built once; graph static across layers)
__device__ int g_rowptr[5 * (NOP + 1)];
__device__ int g_srcs[5 * EMAX];         // src node per sorted edge
__device__ int g_epos[5 * EMAX];         // orig edge -> sorted position
__device__ int g_cnt[NOP];
__device__ int g_cursor[NOP];
// BN
__device__ double g_sum[3 * HID];
__device__ double g_sumsq[3 * HID];
__device__ float g_scale[3 * HID];
__device__ float g_shift[3 * HID];

// ---------------- fold kernel ----------------
__global__ void fold_kernel(const float* __restrict__ Wg, const float* __restrict__ att_s,
                            const float* __restrict__ att_d, const float* __restrict__ Wge,
                            const float* __restrict__ att_e, const float* __restrict__ We_proj,
                            const float* __restrict__ be_proj) {
    int slot = blockIdx.x;
    int i = slot / 5, t = slot % 5;
    int H = (i < NLAYERS - 1) ? 8 : 1;
    int C = HID / H;
    int k = threadIdx.x;
    const float* Wg_  = Wg  + (size_t)slot * HID * HID;
    const float* Wge_ = Wge + (size_t)slot * HID * HID;
    const float* as_  = att_s + slot * HID;
    const float* ad_  = att_d + slot * HID;
    const float* ae_  = att_e + slot * HID;

    float ws[8] = {0,0,0,0,0,0,0,0};
    float wd[8] = {0,0,0,0,0,0,0,0};
    float we[8] = {0,0,0,0,0,0,0,0};
    for (int j = 0; j < HID; j++) {
        int h = j / C;
        float w1 = Wg_[k * HID + j];
        ws[h] += w1 * as_[j];
        wd[h] += w1 * ad_[j];
        float w2 = Wge_[k * HID + j];
        we[h] += w2 * ae_[j];
    }
    #pragma unroll
    for (int h = 0; h < 8; h++) {
        g_ws[slot * HID * 8 + k * 8 + h] = ws[h];
        g_wd[slot * HID * 8 + k * 8 + h] = wd[h];
    }
    __shared__ float wef[HID * 8];
    #pragma unroll
    for (int h = 0; h < 8; h++) wef[k * 8 + h] = we[h];
    __syncthreads();

    if (k < 32) {
        const float* Wep = We_proj + (size_t)t * 32 * HID + (size_t)k * HID;
        float me[8] = {0,0,0,0,0,0,0,0};
        for (int j = 0; j < HID; j++) {
            float v = Wep[j];
            #pragma unroll
            for (int h = 0; h < 8; h++) me[h] += v * wef[j * 8 + h];
        }
        #pragma unroll
        for (int h = 0; h < 8; h++) g_Me[slot * 32 * 8 + k * 8 + h] = me[h];
    }
    if (k == 32) {
        const float* bep = be_proj + t * HID;
        float ce[8] = {0,0,0,0,0,0,0,0};
        for (int j = 0; j < HID; j++) {
            float v = bep[j];
            #pragma unroll
            for (int h = 0; h < 8; h++) ce[h] += v * wef[j * 8 + h];
        }
        #pragma unroll
        for (int h = 0; h < 8; h++) g_ce[slot * 8 + h] = ce[h];
    }
}

// ---------------- pack Wcat: concat Wg[i,{0,1,4}] along N ----------------
__global__ void pack_wcat(const float* __restrict__ Wg) {
    int idx = blockIdx.x * blockDim.x + threadIdx.x;
    if (idx >= 3 * HID * 384) return;
    int i = idx / (HID * 384);
    int rem = idx % (HID * 384);
    int k = rem / 384, c = rem % 384;
    int r = c / 128, j = c % 128;
    const int tsel[3] = {0, 1, 4};
    g_Wcat[idx] = Wg[(((size_t)(i * 5 + tsel[r])) * HID + k) * HID + j];
}

// ---------------- GEMM: C[M,N] = A[M,K] @ B[K,N] (+bias), K%8==0, N%128==0 ----------------
__global__ __launch_bounds__(256) void gemm2(const float* __restrict__ A,
                                             const float* __restrict__ B,
                                             const float* __restrict__ bias,
                                             float* __restrict__ C,
                                             int M, int K, int N) {
    __shared__ float As[8][128];
    __shared__ float Bs[8][128];
    int tid = threadIdx.x;
    int tx = tid & 15, ty = tid >> 4;
    int row0 = blockIdx.x * 128, col0 = blockIdx.y * 128;
    int arow = tid >> 1, akoff = (tid & 1) * 4;
    int bk = tid >> 5, bcol = (tid & 31) * 4;

    float acc[8][8];
    #pragma unroll
    for (int r = 0; r < 8; r++)
        #pragma unroll
        for (int c = 0; c < 8; c++) acc[r][c] = 0.f;

    for (int kk = 0; kk < K; kk += 8) {
        float4 av = make_float4(0.f, 0.f, 0.f, 0.f);
        int gr = row0 + arow;
        if (gr < M) av = *reinterpret_cast<const float4*>(A + (size_t)gr * K + kk + akoff);
        As[akoff + 0][arow] = av.x;
        As[akoff + 1][arow] = av.y;
        As[akoff + 2][arow] = av.z;
        As[akoff + 3][arow] = av.w;
        *reinterpret_cast<float4*>(&Bs[bk][bcol]) =
            *reinterpret_cast<const float4*>(B + (size_t)(kk + bk) * N + col0 + bcol);
        __syncthreads();
        #pragma unroll
        for (int k = 0; k < 8; k++) {
            float a[8], b[8];
            *(float4*)&a[0] = *(const float4*)&As[k][ty * 4];
            *(float4*)&a[4] = *(const float4*)&As[k][64 + ty * 4];
            *(float4*)&b[0] = *(const float4*)&Bs[k][tx * 4];
            *(float4*)&b[4] = *(const float4*)&Bs[k][64 + tx * 4];
            #pragma unroll
            for (int r = 0; r < 8; r++)
                #pragma unroll
                for (int c = 0; c < 8; c++) acc[r][c] += a[r] * b[c];
        }
        __syncthreads();
    }
    #pragma unroll
    for (int ri = 0; ri < 2; ri++) {
        #pragma unroll
        for (int r = 0; r < 4; r++) {
            int gr = row0 + ri * 64 + ty * 4 + r;
            if (gr >= M) continue;
            #pragma unroll
            for (int ci = 0; ci < 2; ci++) {
                int gc = col0 + ci * 64 + tx * 4;
                float4 v;
                v.x = acc[ri * 4 + r][ci * 4 + 0];
                v.y = acc[ri * 4 + r][ci * 4 + 1];
                v.z = acc[ri * 4 + r][ci * 4 + 2];
                v.w = acc[ri * 4 + r][ci * 4 + 3];
                if (bias) {
                    v.x += bias[gc + 0]; v.y += bias[gc + 1];
                    v.z += bias[gc + 2]; v.w += bias[gc + 3];
                }
                *reinterpret_cast<float4*>(C + (size_t)gr * N + gc) = v;
            }
        }
    }
}

// ---------------- node dot ----------------
__global__ void node_dot_kernel(const float* __restrict__ x, const float* __restrict__ w,
                                float* __restrict__ out, int n, int H) {
    int gw = (blockIdx.x * blockDim.x + threadIdx.x) >> 5;
    int lane = threadIdx.x & 31;
    if (gw >= n) return;
    const float* xr = x + (size_t)gw * HID;
    float acc[8] = {0,0,0,0,0,0,0,0};
    for (int k = lane; k < HID; k += 32) {
        float xv = xr[k];
        #pragma unroll
        for (int h = 0; h < 8; h++) acc[h] += xv * w[k * 8 + h];
    }
    #pragma unroll
    for (int off = 16; off > 0; off >>= 1)
        #pragma unroll
        for (int h = 0; h < 8; h++) acc[h] += __shfl_xor_sync(FULLMASK, acc[h], off);
    if (lane == 0)
        for (int h = 0; h < H; h++) out[gw * H + h] = acc[h];
}

// ---------------- a_e (writes CSR-sorted) ----------------
__global__ void edge_ae_kernel(const float* __restrict__ ea, const float* __restrict__ Me,
                               const float* __restrict__ ce, const int* __restrict__ epos,
                               float* __restrict__ out, int E, int H) {
    __shared__ float sMe[32 * 8];
    __shared__ float sce[8];
    int tid = threadIdx.x;
    if (tid < 256) sMe[tid] = Me[tid];
    if (tid < 8) sce[tid] = ce[tid];
    __syncthreads();
    int e = blockIdx.x * blockDim.x + tid;
    if (e >= E) return;
    const float* er = ea + (size_t)e * 32;
    float acc[8];
    #pragma unroll
    for (int h = 0; h < 8; h++) acc[h] = sce[h];
    #pragma unroll 8
    for (int k = 0; k < 32; k++) {
        float v = er[k];
        #pragma unroll
        for (int h = 0; h < 8; h++) acc[h] += v * sMe[k * 8 + h];
    }
    int pos = epos[e];
    for (int h = 0; h < H; h++) out[pos * H + h] = acc[h];
}

// ---------------- CSR build ----------------
__global__ void zero_int_kernel(int* p, int n) {
    int i = blockIdx.x * blockDim.x + threadIdx.x;
    if (i < n) p[i] = 0;
}
__global__ void hist_kernel(const int* __restrict__ EI, int E, int* __restrict__ cnt) {
    int e = blockIdx.x * blockDim.x + threadIdx.x;
    if (e < E) atomicAdd(&cnt[EI[E + e]], 1);
}
__global__ void scan_kernel(const int* __restrict__ cnt, int* __restrict__ rowptr, int n) {
    __shared__ int sh[1024];
    __shared__ int base;
    int tid = threadIdx.x;
    if (tid == 0) base = 0;
    __syncthreads();
    for (int i0 = 0; i0 < n; i0 += 1024) {
        int i = i0 + tid;
        int v = (i < n) ? cnt[i] : 0;
        sh[tid] = v;
        __syncthreads();
        for (int off = 1; off < 1024; off <<= 1) {
            int t = (tid >= off) ? sh[tid - off] : 0;
            __syncthreads();
            sh[tid] += t;
            __syncthreads();
        }
        if (i < n) rowptr[i] = base + sh[tid] - v;
        __syncthreads();
        if (tid == 1023) base += sh[1023];
        __syncthreads();
    }
    if (tid == 0) rowptr[n] = base;
}
__global__ void scatter_kernel(const int* __restrict__ EI, int E,
                               const int* __restrict__ rowptr, int* __restrict__ cursor,
                               int* __restrict__ srcs, int* __restrict__ epos) {
    int e = blockIdx.x * blockDim.x + threadIdx.x;
    if (e >= E) return;
    int dst = EI[E + e];
    int pos = rowptr[dst] + atomicAdd(&cursor[dst], 1);
    srcs[pos] = EI[e];
    epos[e] = pos;
}

// ---------------- fused gather: online softmax + weighted sum, warp per dst ----------------
__global__ void gat_gather(const float* __restrict__ xs, int rs,
                           const int* __restrict__ rowptr,
                           const int* __restrict__ srcs,
                           const float* __restrict__ aes,
                           const float* __restrict__ as_,
                           const float* __restrict__ ad_,
                           float* __restrict__ agg,
                           int ndst, int H) {
    int w = (blockIdx.x * blockDim.x + threadIdx.x) >> 5;
    int lane = threadIdx.x & 31;
    if (w >= ndst) return;
    int beg = rowptr[w], end = rowptr[w + 1];
    int hl = (lane * 4 * H) >> 7;  // head owning this lane's 4 columns
    float adv = (lane < H) ? ad_[w * H + lane] : 0.f;
    float4 acc = make_float4(0.f, 0.f, 0.f, 0.f);
    float m = -1e30f, den = 0.f;
    for (int p = beg; p < end; p++) {
        int s = srcs[p];
        float lg = 0.f;
        if (lane < H) {
            lg = as_[s * H + lane] + adv + aes[p * H + lane];
            lg = lg > 0.f ? lg : 0.2f * lg;
        }
        float le = __shfl_sync(FULLMASK, lg, hl);
        if (le > m) {
            float sc = __expf(m - le);
            acc.x *= sc; acc.y *= sc; acc.z *= sc; acc.w *= sc;
            den *= sc;
            m = le;
        }
        float wv = __expf(le - m);
        den += wv;
        const float4 xv = *reinterpret_cast<const float4*>(xs + (size_t)s * rs + lane * 4);
        acc.x += wv * xv.x; acc.y += wv * xv.y;
        acc.z += wv * xv.z; acc.w += wv * xv.w;
    }
    float inv = 1.f / (den + 1e-16f);
    float4* op = reinterpret_cast<float4*>(agg + (size_t)w * HID + lane * 4);
    float4 cur = *op;
    cur.x += acc.x * inv; cur.y += acc.y * inv;
    cur.z += acc.z * inv; cur.w += acc.w * inv;
    *op = cur;
}

// ---------------- init agg with per-type bias sums; zero BN stats ----------------
__global__ void init_agg_kernel(const float* __restrict__ bg, int layer) {
    int idx = blockIdx.x * blockDim.x + threadIdx.x;
    if (idx < 3 * HID) { g_sum[idx] = 0.0; g_sumsq[idx] = 0.0; }
    if (idx >= NALL * HID) return;
    int row = idx / HID, col = idx % HID;
    const float* b = bg + layer * 5 * HID;
    float v;
    if (row < NOP)            v = b[0 * HID + col] + b[2 * HID + col] + b[3 * HID + col];
    else if (row < NOP + NMA) v = b[1 * HID + col];
    else                      v = b[4 * HID + col];
    g_agg[idx] = v;
}

// ---------------- BN ----------------
__global__ void bn_stats_kernel() {
    const int offs[3] = {0, NOP, NOP + NMA};
    const int cnts[3] = {NOP, NMA, NJOB};
    int type = blockIdx.y;
    int col = threadIdx.x;
    int N = cnts[type], off = offs[type];
    double s = 0.0, s2 = 0.0;
    for (int r = blockIdx.x; r < N; r += gridDim.x) {
        float v = g_agg[(size_t)(off + r) * HID + col];
        s += (double)v;
        s2 += (double)v * (double)v;
    }
    atomicAdd(&g_sum[type * HID + col], s);
    atomicAdd(&g_sumsq[type * HID + col], s2);
}

__global__ void bn_finalize_kernel(const float* __restrict__ gamma,
                                   const float* __restrict__ beta, int layer) {
    const int cnts[3] = {NOP, NMA, NJOB};
    int idx = threadIdx.x + blockIdx.x * blockDim.x;
    if (idx >= 3 * HID) return;
    int type = idx / HID, col = idx % HID;
    double N = (double)cnts[type];
    double mu = g_sum[idx] / N;
    double var = g_sumsq[idx] / N - mu * mu;
    if (var < 0.0) var = 0.0;
    float g = gamma[layer * 3 * HID + type * HID + col];
    float b = beta[layer * 3 * HID + type * HID + col];
    float sc = g * rsqrtf((float)var + 1e-5f);
    g_scale[idx] = sc;
    g_shift[idx] = b - (float)mu * sc;
}

__global__ void bn_apply_kernel(int layer) {
    int idx = blockIdx.x * blockDim.x + threadIdx.x;
    if (idx >= NALL * HID) return;
    int row = idx / HID, col = idx % HID;
    int type = (row < NOP) ? 0 : ((row < NOP + NMA) ? 1 : 2);
    float v = g_agg[idx] * g_scale[type * HID + col] + g_shift[type * HID + col];
    if (layer < NLAYERS - 1) v = fmaxf(v, 0.f);
    g_x[idx] = g_x[idx] + v;
}

// ---------------- launch ----------------
extern "C" void kernel_launch(void* const* d_in, const int* in_sizes, int n_in,
                              void* d_out, int out_size) {
    const float* x_op  = (const float*)d_in[0];
    const float* x_ma  = (const float*)d_in[1];
    const float* x_job = (const float*)d_in[2];

    const int* EI[5];
    const float* EA[5];
    bool interleaved = (in_sizes[4] > 1000000);
    if (interleaved) {
        for (int t = 0; t < 5; t++) {
            EI[t] = (const int*)d_in[3 + 2 * t];
            EA[t] = (const float*)d_in[4 + 2 * t];
        }
    } else {
        for (int t = 0; t < 5; t++) {
            EI[t] = (const int*)d_in[3 + t];
            EA[t] = (const float*)d_in[8 + t];
        }
    }

    const float* Wn_op = (const float*)d_in[13];
    const float* bn_op = (const float*)d_in[14];
    const float* Wn_ma = (const float*)d_in[15];
    const float* bn_ma = (const float*)d_in[16];
    const float* Wn_job = (const float*)d_in[17];
    const float* bn_job = (const float*)d_in[18];
    const float* We_proj = (const float*)d_in[19];
    const float* be_proj = (const float*)d_in[20];
    const float* Wg    = (const float*)d_in[21];
    const float* att_s = (const float*)d_in[22];
    const float* att_d = (const float*)d_in[23];
    const float* Wge   = (const float*)d_in[24];
    const float* att_e = (const float*)d_in[25];
    const float* bg    = (const float*)d_in[26];
    const float* gamma = (const float*)d_in[27];
    const float* beta  = (const float*)d_in[28];
    const float* Wo    = (const float*)d_in[29];
    const float* bo    = (const float*)d_in[30];

    static const int Esz[5]  = {150000, 100000, 150000, 100000, 100000};
    static const int Tsrc[5] = {0, 0, 1, 2, 0};
    static const int Tdst[5] = {0, 1, 0, 0, 2};
    static const int offn[3] = {0, NOP, NOP + NMA};
    static const int cntn[3] = {NOP, NMA, NJOB};

    float* gx;    cudaGetSymbolAddress((void**)&gx, g_x);
    float* gxs3;  cudaGetSymbolAddress((void**)&gxs3, g_xs3);
    float* gxsm;  cudaGetSymbolAddress((void**)&gxsm, g_xsm);
    float* gxsj;  cudaGetSymbolAddress((void**)&gxsj, g_xsj);
    float* gas;   cudaGetSymbolAddress((void**)&gas, g_as);
    float* gad;   cudaGetSymbolAddress((void**)&gad, g_ad);
    float* gaes;  cudaGetSymbolAddress((void**)&gaes, g_aes);
    float* gws;   cudaGetSymbolAddress((void**)&gws, g_ws);
    float* gwd;   cudaGetSymbolAddress((void**)&gwd, g_wd);
    float* gMe;   cudaGetSymbolAddress((void**)&gMe, g_Me);
    float* gce;   cudaGetSymbolAddress((void**)&gce, g_ce);
    float* gWcat; cudaGetSymbolAddress((void**)&gWcat, g_Wcat);
    float* gagg;  cudaGetSymbolAddress((void**)&gagg, g_agg);
    int* grp;     cudaGetSymbolAddress((void**)&grp, g_rowptr);
    int* gsrc;    cudaGetSymbolAddress((void**)&gsrc, g_srcs);
    int* gep;     cudaGetSymbolAddress((void**)&gep, g_epos);
    int* gcnt;    cudaGetSymbolAddress((void**)&gcnt, g_cnt);
    int* gcur;    cudaGetSymbolAddress((void**)&gcur, g_cursor);

    // ---- prep: folds + weight concat + CSR build (graph static across layers) ----
    fold_kernel<<<15, 128>>>(Wg, att_s, att_d, Wge, att_e, We_proj, be_proj);
    pack_wcat<<<(3 * HID * 384 + 255) / 256, 256>>>(Wg);
    for (int t = 0; t < 5; t++) {
        int E = Esz[t];
        int ndst = cntn[Tdst[t]];
        zero_int_kernel<<<(ndst + 255) / 256, 256>>>(gcnt, ndst);
        hist_kernel<<<(E + 255) / 256, 256>>>(EI[t], E, gcnt);
        scan_kernel<<<1, 1024>>>(gcnt, grp + t * (NOP + 1), ndst);
        zero_int_kernel<<<(ndst + 255) / 256, 256>>>(gcur, ndst);
        scatter_kernel<<<(E + 255) / 256, 256>>>(EI[t], E, grp + t * (NOP + 1), gcur,
                                                 gsrc + t * EMAX, gep + t * EMAX);
    }

    // ---- input projections ----
    gemm2<<<dim3((NOP + 127) / 128, 1), 256>>>(x_op, Wn_op, bn_op, gx, NOP, 64, 128);
    gemm2<<<dim3((NMA + 127) / 128, 1), 256>>>(x_ma, Wn_ma, bn_ma, gx + (size_t)NOP * HID, NMA, 32, 128);
    gemm2<<<dim3((NJOB + 127) / 128, 1), 256>>>(x_job, Wn_job, bn_job, gx + (size_t)(NOP + NMA) * HID, NJOB, 16, 128);

    // ---- layers ----
    for (int i = 0; i < NLAYERS; i++) {
        int H = (i < NLAYERS - 1) ? 8 : 1;
        init_agg_kernel<<<(NALL * HID + 255) / 256, 256>>>(bg, i);
        // merged src projections for op-src relations {0,1,4}
        gemm2<<<dim3((NOP + 127) / 128, 3), 256>>>(gx, gWcat + (size_t)i * HID * 384,
                                                   nullptr, gxs3, NOP, 128, 384);
        gemm2<<<dim3((NMA + 127) / 128, 1), 256>>>(gx + (size_t)NOP * HID,
                                                   Wg + (size_t)(i * 5 + 2) * HID * HID,
                                                   nullptr, gxsm, NMA, 128, 128);
        gemm2<<<dim3((NJOB + 127) / 128, 1), 256>>>(gx + (size_t)(NOP + NMA) * HID,
                                                    Wg + (size_t)(i * 5 + 3) * HID * HID,
                                                    nullptr, gxsj, NJOB, 128, 128);
        for (int t = 0; t < 5; t++) {
            int slot = i * 5 + t;
            int st = Tsrc[t], dt = Tdst[t];
            int E = Esz[t];
            int nsrc = cntn[st], ndst = cntn[dt];
            const float* xsrc = gx + (size_t)offn[st] * HID;
            const float* xdst = gx + (size_t)offn[dt] * HID;
            node_dot_kernel<<<(nsrc * 32 + 255) / 256, 256>>>(xsrc, gws + slot * HID * 8, gas, nsrc, H);
            node_dot_kernel<<<(ndst * 32 + 255) / 256, 256>>>(xdst, gwd + slot * HID * 8, gad, ndst, H);
            edge_ae_kernel<<<(E + 255) / 256, 256>>>(EA[t], gMe + slot * 32 * 8, gce + slot * 8,
                                                     gep + t * EMAX, gaes, E, H);
            const float* xs;
            int rs;
            if (t == 0)      { xs = gxs3;        rs = 384; }
            else if (t == 1) { xs = gxs3 + 128;  rs = 384; }
            else if (t == 4) { xs = gxs3 + 256;  rs = 384; }
            else if (t == 2) { xs = gxsm;        rs = 128; }
            else             { xs = gxsj;        rs = 128; }
            gat_gather<<<(ndst * 32 + 255) / 256, 256>>>(xs, rs, grp + t * (NOP + 1),
                                                         gsrc + t * EMAX, gaes, gas, gad,
                                                         gagg + (size_t)offn[dt] * HID, ndst, H);
        }
        dim3 sg(64, 3);
        bn_stats_kernel<<<sg, 128>>>();
        bn_finalize_kernel<<<2, 256>>>(gamma, beta, i);
        bn_apply_kernel<<<(NALL * HID + 255) / 256, 256>>>(i);
    }

    // ---- output projection ----
    gemm2<<<dim3((NOP + 127) / 128, 1), 256>>>(gx, Wo, bo, (float*)d_out, NOP, 128, 128);
}

// round 7
// speedup vs baseline: 1.9048x; 1.4775x over previous
#include <cuda_runtime.h>
#include <math.h>

#define HID 128
#define NOP 50000
#define NMA 1000
#define NJOB 5000
#define NALL 56000
#define NLAYERS 3
#define EMAX 150000
#define FULLMASK 0xffffffffu

// ---------------- device scratch ----------------
__device__ float g_x[NALL * HID];
__device__ float g_agg[NALL * HID];
__device__ float g_xs3[NOP * 384];        // merged src proj for relations 0,1,4
__device__ float g_xsm[NMA * HID];        // src proj relation 2
__device__ float g_xsj[NJOB * HID];       // src proj relation 3
__device__ float g_asL[5 * NOP * 8];      // per-relation src dots
__device__ float g_adL[5 * NOP * 8];      // per-relation dst dots
__device__ float g_aes[5 * EMAX * 8];     // per-relation edge dots (CSR order)
__device__ float g_ws[15 * HID * 8];
__device__ float g_wd[15 * HID * 8];
__device__ float g_Me[15 * 32 * 8];
__device__ float g_ce[15 * 8];
__device__ float g_Wcat[3 * HID * 384];
// CSR
__device__ int g_rowptr[5 * (NOP + 1)];
__device__ int g_srcs[5 * EMAX];
__device__ int g_epos[5 * EMAX];
__device__ int g_cnt[NOP];
__device__ int g_cursor[NOP];
// BN
__device__ double g_part[2 * 3 * 64 * HID];   // [sum/sumsq][type][chunk][col]
__device__ float g_scale[3 * HID];
__device__ float g_shift[3 * HID];

struct DotArgs { const float* w[6]; float* out[6]; int nw; int H; };
struct EAArgs  { const float* ea[5]; };
struct GArgs   { const float* xs[5]; int rs[5]; int H; const float* bg; };

// ---------------- fold kernel ----------------
__global__ void fold_kernel(const float* __restrict__ Wg, const float* __restrict__ att_s,
                            const float* __restrict__ att_d, const float* __restrict__ Wge,
                            const float* __restrict__ att_e, const float* __restrict__ We_proj,
                            const float* __restrict__ be_proj) {
    int slot = blockIdx.x;
    int i = slot / 5, t = slot % 5;
    int H = (i < NLAYERS - 1) ? 8 : 1;
    int C = HID / H;
    int k = threadIdx.x;
    const float* Wg_  = Wg  + (size_t)slot * HID * HID;
    const float* Wge_ = Wge + (size_t)slot * HID * HID;
    const float* as_  = att_s + slot * HID;
    const float* ad_  = att_d + slot * HID;
    const float* ae_  = att_e + slot * HID;

    float ws[8] = {0,0,0,0,0,0,0,0};
    float wd[8] = {0,0,0,0,0,0,0,0};
    float we[8] = {0,0,0,0,0,0,0,0};
    for (int j = 0; j < HID; j++) {
        int h = j / C;
        float w1 = Wg_[k * HID + j];
        ws[h] += w1 * as_[j];
        wd[h] += w1 * ad_[j];
        float w2 = Wge_[k * HID + j];
        we[h] += w2 * ae_[j];
    }
    #pragma unroll
    for (int h = 0; h < 8; h++) {
        g_ws[slot * HID * 8 + k * 8 + h] = ws[h];
        g_wd[slot * HID * 8 + k * 8 + h] = wd[h];
    }
    __shared__ float wef[HID * 8];
    #pragma unroll
    for (int h = 0; h < 8; h++) wef[k * 8 + h] = we[h];
    __syncthreads();

    if (k < 32) {
        const float* Wep = We_proj + (size_t)t * 32 * HID + (size_t)k * HID;
        float me[8] = {0,0,0,0,0,0,0,0};
        for (int j = 0; j < HID; j++) {
            float v = Wep[j];
            #pragma unroll
            for (int h = 0; h < 8; h++) me[h] += v * wef[j * 8 + h];
        }
        #pragma unroll
        for (int h = 0; h < 8; h++) g_Me[slot * 32 * 8 + k * 8 + h] = me[h];
    }
    if (k == 32) {
        const float* bep = be_proj + t * HID;
        float ce[8] = {0,0,0,0,0,0,0,0};
        for (int j = 0; j < HID; j++) {
            float v = bep[j];
            #pragma unroll
            for (int h = 0; h < 8; h++) ce[h] += v * wef[j * 8 + h];
        }
        #pragma unroll
        for (int h = 0; h < 8; h++) g_ce[slot * 8 + h] = ce[h];
    }
}

// ---------------- pack Wcat ----------------
__global__ void pack_wcat(const float* __restrict__ Wg) {
    int idx = blockIdx.x * blockDim.x + threadIdx.x;
    if (idx >= 3 * HID * 384) return;
    int i = idx / (HID * 384);
    int rem = idx % (HID * 384);
    int k = rem / 384, c = rem % 384;
    int r = c / 128, j = c % 128;
    const int tsel[3] = {0, 1, 4};
    g_Wcat[idx] = Wg[(((size_t)(i * 5 + tsel[r])) * HID + k) * HID + j];
}

// ---------------- double-buffered SGEMM: C[M,N]=A[M,K]@B[K,N]+bias, K%16==0, N%128==0 ----------------
__global__ __launch_bounds__(256, 2) void gemm3(const float* __restrict__ A,
                                                const float* __restrict__ B,
                                                const float* __restrict__ bias,
                                                float* __restrict__ C,
                                                int M, int K, int N) {
    __shared__ float As[2][16][132];
    __shared__ float Bs[2][16][128];
    int tid = threadIdx.x;
    int tx = tid & 15, ty = tid >> 4;
    int row0 = blockIdx.x * 128, col0 = blockIdx.y * 128;
    int ar0 = tid >> 2, ak0 = (tid & 3) * 4;
    int bk0 = tid >> 5, bc0 = (tid & 31) * 4;
    float4 pa[2], pb[2];

    // fetch tile kk into registers
    #define FETCH(kk)                                                             \
        _Pragma("unroll")                                                         \
        for (int i = 0; i < 2; i++) {                                             \
            int gr = row0 + ar0 + i * 64;                                         \
            pa[i] = make_float4(0.f, 0.f, 0.f, 0.f);                              \
            if (gr < M) pa[i] = *(const float4*)(A + (size_t)gr * K + (kk) + ak0);\
            pb[i] = *(const float4*)(B + (size_t)((kk) + bk0 + i * 8) * N + col0 + bc0); \
        }
    #define STORE(buf)                                                            \
        _Pragma("unroll")                                                         \
        for (int i = 0; i < 2; i++) {                                             \
            int ar = ar0 + i * 64;                                                \
            As[buf][ak0 + 0][ar] = pa[i].x;  As[buf][ak0 + 1][ar] = pa[i].y;      \
            As[buf][ak0 + 2][ar] = pa[i].z;  As[buf][ak0 + 3][ar] = pa[i].w;      \
            *(float4*)&Bs[buf][bk0 + i * 8][bc0] = pb[i];                         \
        }

    FETCH(0); STORE(0); __syncthreads();

    float acc[8][8];
    #pragma unroll
    for (int r = 0; r < 8; r++)
        #pragma unroll
        for (int c = 0; c < 8; c++) acc[r][c] = 0.f;

    int nt = K >> 4;
    for (int t = 0; t < nt; t++) {
        int buf = t & 1;
        if (t + 1 < nt) { FETCH((t + 1) << 4); }
        #pragma unroll
        for (int k = 0; k < 16; k++) {
            float a[8], b[8];
            *(float4*)&a[0] = *(const float4*)&As[buf][k][ty * 4];
            *(float4*)&a[4] = *(const float4*)&As[buf][k][64 + ty * 4];
            *(float4*)&b[0] = *(const float4*)&Bs[buf][k][tx * 4];
            *(float4*)&b[4] = *(const float4*)&Bs[buf][k][64 + tx * 4];
            #pragma unroll
            for (int r = 0; r < 8; r++)
                #pragma unroll
                for (int c = 0; c < 8; c++) acc[r][c] += a[r] * b[c];
        }
        if (t + 1 < nt) { STORE(buf ^ 1); }
        __syncthreads();
    }
    #pragma unroll
    for (int ri = 0; ri < 2; ri++) {
        #pragma unroll
        for (int r = 0; r < 4; r++) {
            int gr = row0 + ri * 64 + ty * 4 + r;
            if (gr >= M) continue;
            #pragma unroll
            for (int ci = 0; ci < 2; ci++) {
                int gc = col0 + ci * 64 + tx * 4;
                float4 v;
                v.x = acc[ri * 4 + r][ci * 4 + 0];
                v.y = acc[ri * 4 + r][ci * 4 + 1];
                v.z = acc[ri * 4 + r][ci * 4 + 2];
                v.w = acc[ri * 4 + r][ci * 4 + 3];
                if (bias) {
                    v.x += bias[gc + 0]; v.y += bias[gc + 1];
                    v.z += bias[gc + 2]; v.w += bias[gc + 3];
                }
                *(float4*)(C + (size_t)gr * N + gc) = v;
            }
        }
    }
    #undef FETCH
    #undef STORE
}

// ---------------- fused attention dots: all relations for one node type ----------------
__global__ void dots_kernel(const float* __restrict__ x, int n, DotArgs da) {
    __shared__ float sw[6 * 1024];
    int tid = threadIdx.x;
    int tot = da.nw * 1024;
    for (int i = tid; i < tot; i += 256) sw[i] = da.w[i >> 10][i & 1023];
    __syncthreads();
    int node = blockIdx.x * 8 + (tid >> 5);
    int lane = tid & 31;
    if (node >= n) return;
    float xv[4];
    #pragma unroll
    for (int i = 0; i < 4; i++) xv[i] = x[(size_t)node * HID + lane + 32 * i];
    for (int j = 0; j < da.nw; j++) {
        float acc[8] = {0,0,0,0,0,0,0,0};
        #pragma unroll
        for (int i = 0; i < 4; i++) {
            const float* wp = &sw[j * 1024 + (lane + 32 * i) * 8];
            #pragma unroll
            for (int h = 0; h < 8; h++) acc[h] += xv[i] * wp[h];
        }
        #pragma unroll
        for (int off = 16; off > 0; off >>= 1)
            #pragma unroll
            for (int h = 0; h < 8; h++) acc[h] += __shfl_xor_sync(FULLMASK, acc[h], off);
        if (lane == 0)
            for (int h = 0; h < da.H; h++) da.out[j][(size_t)node * da.H + h] = acc[h];
    }
}

// ---------------- batched edge attention dots (all 5 relations) ----------------
__global__ void edge_ae_all(EAArgs ea, const float* __restrict__ Me_base,
                            const float* __restrict__ ce_base, int H) {
    const int Esz[5] = {150000, 100000, 150000, 100000, 100000};
    int t = blockIdx.y;
    int E = Esz[t];
    __shared__ float sMe[256];
    __shared__ float sce[8];
    int tid = threadIdx.x;
    sMe[tid] = Me_base[t * 256 + tid];
    if (tid < 8) sce[tid] = ce_base[t * 8 + tid];
    __syncthreads();
    int e = blockIdx.x * 256 + tid;
    if (e >= E) return;
    const float* er = ea.ea[t] + (size_t)e * 32;
    float acc[8];
    #pragma unroll
    for (int h = 0; h < 8; h++) acc[h] = sce[h];
    #pragma unroll 8
    for (int k = 0; k < 32; k++) {
        float v = er[k];
        #pragma unroll
        for (int h = 0; h < 8; h++) acc[h] += v * sMe[k * 8 + h];
    }
    int pos = g_epos[t * EMAX + e];
    float* out = g_aes + (size_t)t * EMAX * 8;
    for (int h = 0; h < H; h++) out[(size_t)pos * H + h] = acc[h];
}

// ---------------- CSR build ----------------
__global__ void zero_int_kernel(int* p, int n) {
    int i = blockIdx.x * blockDim.x + threadIdx.x;
    if (i < n) p[i] = 0;
}
__global__ void hist_kernel(const int* __restrict__ EI, int E, int* __restrict__ cnt) {
    int e = blockIdx.x * blockDim.x + threadIdx.x;
    if (e < E) atomicAdd(&cnt[EI[E + e]], 1);
}
__global__ void scan_kernel(const int* __restrict__ cnt, int* __restrict__ rowptr, int n) {
    __shared__ int sh[1024];
    __shared__ int base;
    int tid = threadIdx.x;
    if (tid == 0) base = 0;
    __syncthreads();
    for (int i0 = 0; i0 < n; i0 += 1024) {
        int i = i0 + tid;
        int v = (i < n) ? cnt[i] : 0;
        sh[tid] = v;
        __syncthreads();
        for (int off = 1; off < 1024; off <<= 1) {
            int t = (tid >= off) ? sh[tid - off] : 0;
            __syncthreads();
            sh[tid] += t;
            __syncthreads();
        }
        if (i < n) rowptr[i] = base + sh[tid] - v;
        __syncthreads();
        if (tid == 1023) base += sh[1023];
        __syncthreads();
    }
    if (tid == 0) rowptr[n] = base;
}
__global__ void scatter_kernel(const int* __restrict__ EI, int E,
                               const int* __restrict__ rowptr, int* __restrict__ cursor,
                               int* __restrict__ srcs, int* __restrict__ epos) {
    int e = blockIdx.x * blockDim.x + threadIdx.x;
    if (e >= E) return;
    int dst = EI[E + e];
    int pos = rowptr[dst] + atomicAdd(&cursor[dst], 1);
    srcs[pos] = EI[e];
    epos[e] = pos;
}

// ---------------- merged gather: all relations, all dst nodes, one launch ----------------
__global__ void gat_gather_all(GArgs ga) {
    int w = (blockIdx.x * blockDim.x + threadIdx.x) >> 5;
    int lane = threadIdx.x & 31;
    if (w >= NALL) return;
    int H = ga.H;
    int hl = (lane * 4 * H) >> 7;
    int nrel, rels[3], node;
    float4 tot;
    const float* bgp = ga.bg;
    if (w < NOP) {
        node = w; nrel = 3; rels[0] = 0; rels[1] = 2; rels[2] = 3;
        float4 b0 = *(const float4*)(bgp + 0 * HID + lane * 4);
        float4 b2 = *(const float4*)(bgp + 2 * HID + lane * 4);
        float4 b3 = *(const float4*)(bgp + 3 * HID + lane * 4);
        tot = make_float4(b0.x + b2.x + b3.x, b0.y + b2.y + b3.y,
                          b0.z + b2.z + b3.z, b0.w + b2.w + b3.w);
    } else if (w < NOP + NMA) {
        node = w - NOP; nrel = 1; rels[0] = 1;
        tot = *(const float4*)(bgp + 1 * HID + lane * 4);
    } else {
        node = w - NOP - NMA; nrel = 1; rels[0] = 4;
        tot = *(const float4*)(bgp + 4 * HID + lane * 4);
    }
    for (int ri = 0; ri < nrel; ri++) {
        int r = rels[ri];
        const int* rp = g_rowptr + r * (NOP + 1);
        int beg = rp[node], end = rp[node + 1];
        const int* sr = g_srcs + r * EMAX;
        const float* aes = g_aes + (size_t)r * EMAX * 8;
        const float* asb = g_asL + (size_t)r * NOP * 8;
        float adv = (lane < H) ? g_adL[(size_t)r * NOP * 8 + (size_t)node * H + lane] : 0.f;
        const float* xs = ga.xs[r];
        int rs = ga.rs[r];
        float m = -1e30f, den = 0.f;
        float4 acc = make_float4(0.f, 0.f, 0.f, 0.f);
        for (int p = beg; p < end; p++) {
            int s = sr[p];
            float lg = 0.f;
            if (lane < H) {
                lg = asb[(size_t)s * H + lane] + adv + aes[(size_t)p * H + lane];
                lg = lg > 0.f ? lg : 0.2f * lg;
            }
            float le = __shfl_sync(FULLMASK, lg, hl);
            if (le > m) {
                float sc = __expf(m - le);
                acc.x *= sc; acc.y *= sc; acc.z *= sc; acc.w *= sc;
                den *= sc;
                m = le;
            }
            float wv = __expf(le - m);
            den += wv;
            const float4 xv = *(const float4*)(xs + (size_t)s * rs + lane * 4);
            acc.x += wv * xv.x; acc.y += wv * xv.y;
            acc.z += wv * xv.z; acc.w += wv * xv.w;
        }
        float inv = 1.f / (den + 1e-16f);
        tot.x += acc.x * inv; tot.y += acc.y * inv;
        tot.z += acc.z * inv; tot.w += acc.w * inv;
    }
    *(float4*)(g_agg + (size_t)w * HID + lane * 4) = tot;
}

// ---------------- BN: deterministic partials (no atomics, no zero pass) ----------------
__global__ void bn_stats_kernel() {
    const int offs[3] = {0, NOP, NOP + NMA};
    const int cnts[3] = {NOP, NMA, NJOB};
    int type = blockIdx.y;
    int col = threadIdx.x;
    int N = cnts[type], off = offs[type];
    double s = 0.0, s2 = 0.0;
    for (int r = blockIdx.x; r < N; r += 64) {
        float v = g_agg[(size_t)(off + r) * HID + col];
        s += (double)v;
        s2 += (double)v * (double)v;
    }
    g_part[((0 * 3 + type) * 64 + blockIdx.x) * HID + col] = s;
    g_part[((1 * 3 + type) * 64 + blockIdx.x) * HID + col] = s2;
}

__global__ void bn_finalize_kernel(const float* __restrict__ gamma,
                                   const float* __restrict__ beta, int layer) {
    const int cnts[3] = {NOP, NMA, NJOB};
    int idx = threadIdx.x + blockIdx.x * blockDim.x;
    if (idx >= 3 * HID) return;
    int type = idx / HID, col = idx % HID;
    double s = 0.0, s2 = 0.0;
    for (int c = 0; c < 64; c++) {
        s  += g_part[((0 * 3 + type) * 64 + c) * HID + col];
        s2 += g_part[((1 * 3 + type) * 64 + c) * HID + col];
    }
    double N = (double)cnts[type];
    double mu = s / N;
    double var = s2 / N - mu * mu;
    if (var < 0.0) var = 0.0;
    float g = gamma[layer * 3 * HID + type * HID + col];
    float b = beta[layer * 3 * HID + type * HID + col];
    float sc = g * rsqrtf((float)var + 1e-5f);
    g_scale[idx] = sc;
    g_shift[idx] = b - (float)mu * sc;
}

__global__ void bn_apply_kernel(int layer) {
    int idx = blockIdx.x * blockDim.x + threadIdx.x;
    if (idx >= NALL * HID) return;
    int row = idx / HID, col = idx % HID;
    int type = (row < NOP) ? 0 : ((row < NOP + NMA) ? 1 : 2);
    float v = g_agg[idx] * g_scale[type * HID + col] + g_shift[type * HID + col];
    if (layer < NLAYERS - 1) v = fmaxf(v, 0.f);
    g_x[idx] = g_x[idx] + v;
}

// ---------------- launch ----------------
extern "C" void kernel_launch(void* const* d_in, const int* in_sizes, int n_in,
                              void* d_out, int out_size) {
    const float* x_op  = (const float*)d_in[0];
    const float* x_ma  = (const float*)d_in[1];
    const float* x_job = (const float*)d_in[2];

    const int* EI[5];
    const float* EA[5];
    bool interleaved = (in_sizes[4] > 1000000);
    if (interleaved) {
        for (int t = 0; t < 5; t++) {
            EI[t] = (const int*)d_in[3 + 2 * t];
            EA[t] = (const float*)d_in[4 + 2 * t];
        }
    } else {
        for (int t = 0; t < 5; t++) {
            EI[t] = (const int*)d_in[3 + t];
            EA[t] = (const float*)d_in[8 + t];
        }
    }

    const float* Wn_op = (const float*)d_in[13];
    const float* bn_op = (const float*)d_in[14];
    const float* Wn_ma = (const float*)d_in[15];
    const float* bn_ma = (const float*)d_in[16];
    const float* Wn_job = (const float*)d_in[17];
    const float* bn_job = (const float*)d_in[18];
    const float* We_proj = (const float*)d_in[19];
    const float* be_proj = (const float*)d_in[20];
    const float* Wg    = (const float*)d_in[21];
    const float* att_s = (const float*)d_in[22];
    const float* att_d = (const float*)d_in[23];
    const float* Wge   = (const float*)d_in[24];
    const float* att_e = (const float*)d_in[25];
    const float* bg    = (const float*)d_in[26];
    const float* gamma = (const float*)d_in[27];
    const float* beta  = (const float*)d_in[28];
    const float* Wo    = (const float*)d_in[29];
    const float* bo    = (const float*)d_in[30];

    static const int Esz[5]  = {150000, 100000, 150000, 100000, 100000};
    static const int Tdst[5] = {0, 1, 0, 0, 2};
    static const int cntn[3] = {NOP, NMA, NJOB};

    float* gx;    cudaGetSymbolAddress((void**)&gx, g_x);
    float* gxs3;  cudaGetSymbolAddress((void**)&gxs3, g_xs3);
    float* gxsm;  cudaGetSymbolAddress((void**)&gxsm, g_xsm);
    float* gxsj;  cudaGetSymbolAddress((void**)&gxsj, g_xsj);
    float* gasL;  cudaGetSymbolAddress((void**)&gasL, g_asL);
    float* gadL;  cudaGetSymbolAddress((void**)&gadL, g_adL);
    float* gws;   cudaGetSymbolAddress((void**)&gws, g_ws);
    float* gwd;   cudaGetSymbolAddress((void**)&gwd, g_wd);
    float* gMe;   cudaGetSymbolAddress((void**)&gMe, g_Me);
    float* gce;   cudaGetSymbolAddress((void**)&gce, g_ce);
    float* gWcat; cudaGetSymbolAddress((void**)&gWcat, g_Wcat);
    int* grp;     cudaGetSymbolAddress((void**)&grp, g_rowptr);
    int* gsrc;    cudaGetSymbolAddress((void**)&gsrc, g_srcs);
    int* gep;     cudaGetSymbolAddress((void**)&gep, g_epos);
    int* gcnt;    cudaGetSymbolAddress((void**)&gcnt, g_cnt);
    int* gcur;    cudaGetSymbolAddress((void**)&gcur, g_cursor);

    // ---- prep ----
    fold_kernel<<<15, 128>>>(Wg, att_s, att_d, Wge, att_e, We_proj, be_proj);
    pack_wcat<<<(3 * HID * 384 + 255) / 256, 256>>>(Wg);
    for (int t = 0; t < 5; t++) {
        int E = Esz[t];
        int ndst = cntn[Tdst[t]];
        zero_int_kernel<<<(ndst + 255) / 256, 256>>>(gcnt, ndst);
        hist_kernel<<<(E + 255) / 256, 256>>>(EI[t], E, gcnt);
        scan_kernel<<<1, 1024>>>(gcnt, grp + t * (NOP + 1), ndst);
        zero_int_kernel<<<(ndst + 255) / 256, 256>>>(gcur, ndst);
        scatter_kernel<<<(E + 255) / 256, 256>>>(EI[t], E, grp + t * (NOP + 1), gcur,
                                                 gsrc + t * EMAX, gep + t * EMAX);
    }

    // ---- input projections ----
    gemm3<<<dim3((NOP + 127) / 128, 1), 256>>>(x_op, Wn_op, bn_op, gx, NOP, 64, 128);
    gemm3<<<dim3((NMA + 127) / 128, 1), 256>>>(x_ma, Wn_ma, bn_ma, gx + (size_t)NOP * HID, NMA, 32, 128);
    gemm3<<<dim3((NJOB + 127) / 128, 1), 256>>>(x_job, Wn_job, bn_job, gx + (size_t)(NOP + NMA) * HID, NJOB, 16, 128);

    EAArgs eaa;
    for (int t = 0; t < 5; t++) eaa.ea[t] = EA[t];

    // ---- layers ----
    for (int i = 0; i < NLAYERS; i++) {
        int H = (i < NLAYERS - 1) ? 8 : 1;
        int b = i * 5;
        // src projections
        gemm3<<<dim3((NOP + 127) / 128, 3), 256>>>(gx, gWcat + (size_t)i * HID * 384,
                                                   nullptr, gxs3, NOP, 128, 384);
        gemm3<<<dim3((NMA + 127) / 128, 1), 256>>>(gx + (size_t)NOP * HID,
                                                   Wg + (size_t)(b + 2) * HID * HID,
                                                   nullptr, gxsm, NMA, 128, 128);
        gemm3<<<dim3((NJOB + 127) / 128, 1), 256>>>(gx + (size_t)(NOP + NMA) * HID,
                                                    Wg + (size_t)(b + 3) * HID * HID,
                                                    nullptr, gxsj, NJOB, 128, 128);
        // fused attention dots per node type
        {
            DotArgs da;  // operation: src for 0,1,4 ; dst for 0,2,3
            da.w[0] = gws + (b + 0) * 1024; da.out[0] = gasL + (size_t)0 * NOP * 8;
            da.w[1] = gws + (b + 1) * 1024; da.out[1] = gasL + (size_t)1 * NOP * 8;
            da.w[2] = gws + (b + 4) * 1024; da.out[2] = gasL + (size_t)4 * NOP * 8;
            da.w[3] = gwd + (b + 0) * 1024; da.out[3] = gadL + (size_t)0 * NOP * 8;
            da.w[4] = gwd + (b + 2) * 1024; da.out[4] = gadL + (size_t)2 * NOP * 8;
            da.w[5] = gwd + (b + 3) * 1024; da.out[5] = gadL + (size_t)3 * NOP * 8;
            da.nw = 6; da.H = H;
            dots_kernel<<<(NOP + 7) / 8, 256>>>(gx, NOP, da);
        }
        {
            DotArgs da;  // machine: src for 2 ; dst for 1
            da.w[0] = gws + (b + 2) * 1024; da.out[0] = gasL + (size_t)2 * NOP * 8;
            da.w[1] = gwd + (b + 1) * 1024; da.out[1] = gadL + (size_t)1 * NOP * 8;
            da.nw = 2; da.H = H;
            dots_kernel<<<(NMA + 7) / 8, 256>>>(gx + (size_t)NOP * HID, NMA, da);
        }
        {
            DotArgs da;  // job: src for 3 ; dst for 4
            da.w[0] = gws + (b + 3) * 1024; da.out[0] = gasL + (size_t)3 * NOP * 8;
            da.w[1] = gwd + (b + 4) * 1024; da.out[1] = gadL + (size_t)4 * NOP * 8;
            da.nw = 2; da.H = H;
            dots_kernel<<<(NJOB + 7) / 8, 256>>>(gx + (size_t)(NOP + NMA) * HID, NJOB, da);
        }
        // batched edge dots
        edge_ae_all<<<dim3((EMAX + 255) / 256, 5), 256>>>(eaa, gMe + b * 256, gce + b * 8, H);
        // merged gather (writes agg = bias + sum of per-relation softmax aggregates)
        {
            GArgs ga;
            ga.xs[0] = gxs3;        ga.rs[0] = 384;
            ga.xs[1] = gxs3 + 128;  ga.rs[1] = 384;
            ga.xs[2] = gxsm;        ga.rs[2] = 128;
            ga.xs[3] = gxsj;        ga.rs[3] = 128;
            ga.xs[4] = gxs3 + 256;  ga.rs[4] = 384;
            ga.H = H;
            ga.bg = bg + i * 5 * HID;
            gat_gather_all<<<(NALL * 32 + 255) / 256, 256>>>(ga);
        }
        // BN + relu + residual
        bn_stats_kernel<<<dim3(64, 3), 128>>>();
        bn_finalize_kernel<<<2, 256>>>(gamma, beta, i);
        bn_apply_kernel<<<(NALL * HID + 255) / 256, 256>>>(i);
    }

    // ---- output projection ----
    gemm3<<<dim3((NOP + 127) / 128, 1), 256>>>(gx, Wo, bo, (float*)d_out, NOP, 128, 128);
}